// round 4
// baseline (speedup 1.0000x reference)
#include <cuda_runtime.h>
#include <cuda_bf16.h>
#include <cstdint>

// ============================================================================
// GNN_EBM Langevin sampler, collapsed analytic form.
//
// Identity: with s_i = 1 + rowsum(A)_i/66 > 0, q_i = s_i + (A s)_i/66 > 0:
//   h2[:,i] = q_i * relu(h0),  h0 = x@W_in[:64] + z@W_in[64:66] + b_in
//   E = relu(q64 r@WT1 + bT1)@WT2 + relu(q65 r@WY1 + bY1)@WY2 + const
// grad_z E = Wz^T ( 1[h0>0] .* ( Wfold @ (1[a>0] .* vcat) ) )
//   Wfold[d][k] = q0*WT1[d][k] (k<128) | q1*WY1[d][k-128]
//
// RNG: JAX *partitionable* threefry (modern default):
//   split(key,20):  subkey[i] = threefry2x32(k, hi=0, lo=i) -> (o0,o1)
//   bits32(shape):  elem j -> threefry2x32(k, 0, j); bits = o0 ^ o1
// then uniform [-0.99999994, 1) -> sqrt(2)*erfinv (XLA Giles poly).
// ============================================================================

#define MT       32
#define NTHREADS 512
#define NSTEPS   20
#define NBLOCKS  (8192 / MT)
#define WSTRIDE  258   // bf16 elements per W row (padded: conflict-free both axes)

__device__ float g_q[2];
__device__ uint2 g_sub[NSTEPS];

// ---------------------------------------------------------------------------
// threefry2x32 — 20 rounds, 5 key injections
// ---------------------------------------------------------------------------
__device__ __forceinline__ uint32_t rotl32(uint32_t v, int r) {
    return (v << r) | (v >> (32 - r));
}

__device__ __forceinline__ void threefry2x32(uint32_t k0, uint32_t k1,
                                             uint32_t x0, uint32_t x1,
                                             uint32_t& o0, uint32_t& o1) {
    uint32_t k2 = k0 ^ k1 ^ 0x1BD11BDAu;
    x0 += k0; x1 += k1;
#define TFR(r) { x0 += x1; x1 = rotl32(x1, (r)); x1 ^= x0; }
    TFR(13) TFR(15) TFR(26) TFR(6)
    x0 += k1; x1 += k2 + 1u;
    TFR(17) TFR(29) TFR(16) TFR(24)
    x0 += k2; x1 += k0 + 2u;
    TFR(13) TFR(15) TFR(26) TFR(6)
    x0 += k0; x1 += k1 + 3u;
    TFR(17) TFR(29) TFR(16) TFR(24)
    x0 += k1; x1 += k2 + 4u;
    TFR(13) TFR(15) TFR(26) TFR(6)
    x0 += k2; x1 += k0 + 5u;
#undef TFR
    o0 = x0; o1 = x1;
}

// XLA f32 ErfInv (Giles polynomial) — exact lowering of lax.erf_inv
__device__ __forceinline__ float jax_erfinv(float x) {
    float w = -log1pf(-x * x);
    float p;
    if (w < 5.0f) {
        w = w - 2.5f;
        p = 2.81022636e-08f;
        p = fmaf(p, w, 3.43273939e-07f);
        p = fmaf(p, w, -3.5233877e-06f);
        p = fmaf(p, w, -4.39150654e-06f);
        p = fmaf(p, w, 0.00021858087f);
        p = fmaf(p, w, -0.00125372503f);
        p = fmaf(p, w, -0.00417768164f);
        p = fmaf(p, w, 0.246640727f);
        p = fmaf(p, w, 1.50140941f);
    } else {
        w = sqrtf(w) - 3.0f;
        p = -0.000200214257f;
        p = fmaf(p, w, 0.000100950558f);
        p = fmaf(p, w, 0.00134934322f);
        p = fmaf(p, w, -0.00367342844f);
        p = fmaf(p, w, 0.00573950773f);
        p = fmaf(p, w, -0.0076224613f);
        p = fmaf(p, w, 0.00943887047f);
        p = fmaf(p, w, 1.00167406f);
        p = fmaf(p, w, 2.83297682f);
    }
    return p * x;
}

// jax.random.normal from raw bits: uniform in [-0.99999994, 1) then sqrt2*erfinv
__device__ __forceinline__ float jax_normal_from_bits(uint32_t bits) {
    float f = __uint_as_float((bits >> 9) | 0x3f800000u) - 1.0f;
    const float lo = -0.99999994f;
    float u = fmaxf(lo, fmaf(f, 2.0f, lo));   // (hi-lo) rounds to exactly 2.0f
    return 1.41421356237f * jax_erfinv(u);    // = f32(sqrt(2)) 0x3FB504F3
}

__device__ __forceinline__ float bf16lo(uint32_t w) { return __uint_as_float(w << 16); }
__device__ __forceinline__ float bf16hi(uint32_t w) { return __uint_as_float(w & 0xffff0000u); }

// ---------------------------------------------------------------------------
// prep: q scalars + 20 subkeys of jax.random.split(key(42), 20)  [foldlike]
// ---------------------------------------------------------------------------
__device__ __forceinline__ float sigm(float v) { return 1.0f / (1.0f + expf(-v)); }

__global__ void prep_kernel(const float* __restrict__ B) {
    __shared__ float sS[66];
    int t = threadIdx.x;

    if (t < 66) {
        float rs = 0.0f;
        for (int k = 0; k < 66; k++) {
            if (k == t) continue;                 // zero diagonal
            if (t == 65 && k < 64) continue;      // last node: no incoming from x
            rs += sigm(B[t * 66 + k]);
        }
        sS[t] = 1.0f + rs / 66.0f;
    }
    if (t < 20) {
        // foldlike split: counter64 = i -> (hi=0, lo=i); subkey = (o0, o1)
        uint32_t o0, o1;
        threefry2x32(0u, 42u, 0u, (uint32_t)t, o0, o1);
        g_sub[t] = make_uint2(o0, o1);
    }
    __syncthreads();
    if (t == 0) {
        float acc64 = 0.0f;
        for (int j = 0; j < 66; j++)
            if (j != 64) acc64 += sigm(B[64 * 66 + j]) * sS[j];
        float acc65 = sigm(B[65 * 66 + 64]) * sS[64];
        g_q[0] = sS[64] + acc64 / 66.0f;
        g_q[1] = sS[65] + acc65 / 66.0f;
    }
}

// ---------------------------------------------------------------------------
// main persistent kernel
// ---------------------------------------------------------------------------
struct Smem {
    __nv_bfloat16 W[128][WSTRIDE]; // k<128 -> q0*WT1 ; k>=128 -> q1*WY1
    float C[128][36];              // x-part of h0 (+b_in), [d][m]
    float R[128][36];              // relu(h0), [d][m]
    float M[256][36];              // 1[a>0]*vcat, [k][m]  (also prologue scratch)
    float G0[128][36];             // backward partials (k-half 0)
    float G1[128][36];             // backward partials (k-half 1)
    float Wz[2][128];
    float bcat[256];
    float vcat[256];
    float Z[MT][2];
    float Xs[MT][65];
};

__global__ void __launch_bounds__(NTHREADS, 1)
main_kernel(const float* __restrict__ x, const float* __restrict__ tvec,
            const float* __restrict__ Win, const float* __restrict__ bin,
            const float* __restrict__ WT1, const float* __restrict__ bT1,
            const float* __restrict__ WT2,
            const float* __restrict__ WY1, const float* __restrict__ bY1,
            const float* __restrict__ WY2,
            float* __restrict__ out) {
    extern __shared__ unsigned char sraw[];
    Smem& S = *reinterpret_cast<Smem*>(sraw);
    const int tid = threadIdx.x;
    const int b0 = blockIdx.x * MT;
    const float q0 = g_q[0];
    const float q1 = g_q[1];

    // ---- prologue: stage weights ----
    for (int i = tid; i < 128 * 128; i += NTHREADS) {
        int d = i >> 7, k = i & 127;
        S.W[d][k]       = __float2bfloat16(q0 * WT1[i]);
        S.W[d][k + 128] = __float2bfloat16(q1 * WY1[i]);
    }
    float* WinS = &S.M[0][0];                   // scratch: 64x128 f32 = 32KB <= M
    for (int i = tid; i < 64 * 128; i += NTHREADS) WinS[i] = Win[i];
    for (int i = tid; i < MT * 64; i += NTHREADS) {
        int m = i >> 6, e = i & 63;
        S.Xs[m][e] = x[(size_t)(b0 + m) * 64 + e];
    }
    if (tid < 256) {
        S.bcat[tid] = (tid < 128) ? bT1[tid] : bY1[tid - 128];
        S.vcat[tid] = (tid < 128) ? WT2[tid] : WY2[tid - 128];
    }
    if (tid < 128) {
        S.Wz[0][tid] = Win[64 * 128 + tid];
        S.Wz[1][tid] = Win[65 * 128 + tid];
    }
    if (tid < MT) {
        S.Z[tid][0] = tvec[b0 + tid];
        S.Z[tid][1] = 0.0f;
    }
    __syncthreads();

    // ---- C[d][m] = b_in[d] + sum_e Xs[m][e] * Win[e][d] ----
    {
        int d = tid & 127, m0 = (tid >> 7) << 3;
        float acc[8];
        float bv = bin[d];
        #pragma unroll
        for (int i = 0; i < 8; i++) acc[i] = bv;
        for (int e = 0; e < 64; e++) {
            float w = WinS[(e << 7) + d];
            #pragma unroll
            for (int i = 0; i < 8; i++) acc[i] = fmaf(S.Xs[m0 + i][e], w, acc[i]);
        }
        #pragma unroll
        for (int i = 0; i < 8; i++) S.C[d][m0 + i] = acc[i];
    }
    __syncthreads();

    // ---- Langevin steps ----
    for (int s = 0; s < NSTEPS; s++) {
        // Phase A: R = relu(C + z0*Wz0 + z1*Wz1)
        {
            int d = tid >> 2, m0 = (tid & 3) << 3;
            float wz0 = S.Wz[0][d], wz1 = S.Wz[1][d];
            #pragma unroll
            for (int i = 0; i < 8; i++) {
                int m = m0 + i;
                float h = fmaf(S.Z[m][1], wz1, fmaf(S.Z[m][0], wz0, S.C[d][m]));
                S.R[d][m] = fmaxf(h, 0.0f);
            }
        }
        __syncthreads();

        // Phase B: a[m][k] = bcat[k] + sum_d R[d][m]*W[d][k];  M[k][m] = 1[a>0]*vcat[k]
        {
            int mg = tid >> 6, kg = tid & 63;
            int m0 = mg << 2, k0 = kg << 2;
            float a00 = S.bcat[k0],   a01 = S.bcat[k0+1], a02 = S.bcat[k0+2], a03 = S.bcat[k0+3];
            float a10 = a00, a11 = a01, a12 = a02, a13 = a03;
            float a20 = a00, a21 = a01, a22 = a02, a23 = a03;
            float a30 = a00, a31 = a01, a32 = a02, a33 = a03;
            #pragma unroll 4
            for (int d = 0; d < 128; d++) {
                float4 r4 = *reinterpret_cast<const float4*>(&S.R[d][m0]);
                uint32_t w01 = *reinterpret_cast<const uint32_t*>(&S.W[d][k0]);
                uint32_t w23 = *reinterpret_cast<const uint32_t*>(&S.W[d][k0 + 2]);
                float w0 = bf16lo(w01), w1 = bf16hi(w01);
                float w2 = bf16lo(w23), w3 = bf16hi(w23);
                a00 = fmaf(r4.x, w0, a00); a01 = fmaf(r4.x, w1, a01);
                a02 = fmaf(r4.x, w2, a02); a03 = fmaf(r4.x, w3, a03);
                a10 = fmaf(r4.y, w0, a10); a11 = fmaf(r4.y, w1, a11);
                a12 = fmaf(r4.y, w2, a12); a13 = fmaf(r4.y, w3, a13);
                a20 = fmaf(r4.z, w0, a20); a21 = fmaf(r4.z, w1, a21);
                a22 = fmaf(r4.z, w2, a22); a23 = fmaf(r4.z, w3, a23);
                a30 = fmaf(r4.w, w0, a30); a31 = fmaf(r4.w, w1, a31);
                a32 = fmaf(r4.w, w2, a32); a33 = fmaf(r4.w, w3, a33);
            }
            float v0 = S.vcat[k0], v1 = S.vcat[k0+1], v2 = S.vcat[k0+2], v3 = S.vcat[k0+3];
            S.M[k0  ][m0  ] = a00 > 0.f ? v0 : 0.f;
            S.M[k0  ][m0+1] = a10 > 0.f ? v0 : 0.f;
            S.M[k0  ][m0+2] = a20 > 0.f ? v0 : 0.f;
            S.M[k0  ][m0+3] = a30 > 0.f ? v0 : 0.f;
            S.M[k0+1][m0  ] = a01 > 0.f ? v1 : 0.f;
            S.M[k0+1][m0+1] = a11 > 0.f ? v1 : 0.f;
            S.M[k0+1][m0+2] = a21 > 0.f ? v1 : 0.f;
            S.M[k0+1][m0+3] = a31 > 0.f ? v1 : 0.f;
            S.M[k0+2][m0  ] = a02 > 0.f ? v2 : 0.f;
            S.M[k0+2][m0+1] = a12 > 0.f ? v2 : 0.f;
            S.M[k0+2][m0+2] = a22 > 0.f ? v2 : 0.f;
            S.M[k0+2][m0+3] = a32 > 0.f ? v2 : 0.f;
            S.M[k0+3][m0  ] = a03 > 0.f ? v3 : 0.f;
            S.M[k0+3][m0+1] = a13 > 0.f ? v3 : 0.f;
            S.M[k0+3][m0+2] = a23 > 0.f ? v3 : 0.f;
            S.M[k0+3][m0+3] = a33 > 0.f ? v3 : 0.f;
        }
        __syncthreads();

        // Phase C: G_h[d][m] = sum_{k in half h} W[d][k]*M[k][m]   (split-K)
        {
            int h = tid >> 8, dg = (tid >> 3) & 31, mg = tid & 7;
            int d0 = dg << 2, m0 = mg << 2, kb = h << 7;
            float a[4][4];
            #pragma unroll
            for (int i = 0; i < 4; i++)
                #pragma unroll
                for (int j = 0; j < 4; j++) a[i][j] = 0.0f;
            #pragma unroll 2
            for (int kk = 0; kk < 128; kk += 2) {
                int k = kb + kk;
                float4 ma = *reinterpret_cast<const float4*>(&S.M[k][m0]);
                float4 mb = *reinterpret_cast<const float4*>(&S.M[k + 1][m0]);
                #pragma unroll
                for (int di = 0; di < 4; di++) {
                    uint32_t w = *reinterpret_cast<const uint32_t*>(&S.W[d0 + di][k]);
                    float wl = bf16lo(w), wh = bf16hi(w);
                    a[di][0] = fmaf(wl, ma.x, a[di][0]); a[di][0] = fmaf(wh, mb.x, a[di][0]);
                    a[di][1] = fmaf(wl, ma.y, a[di][1]); a[di][1] = fmaf(wh, mb.y, a[di][1]);
                    a[di][2] = fmaf(wl, ma.z, a[di][2]); a[di][2] = fmaf(wh, mb.z, a[di][2]);
                    a[di][3] = fmaf(wl, ma.w, a[di][3]); a[di][3] = fmaf(wh, mb.w, a[di][3]);
                }
            }
            float (*G)[36] = h ? S.G1 : S.G0;
            #pragma unroll
            for (int di = 0; di < 4; di++)
                #pragma unroll
                for (int mi = 0; mi < 4; mi++)
                    G[d0 + di][m0 + mi] = a[di][mi];
        }
        __syncthreads();

        // Phase D: gz[m][c] = sum_d Wz[c][d]*1[R>0]*(G0+G1); z update + noise
        {
            int g = tid >> 3, j = tid & 7;
            int m = g >> 1, c = g & 1;
            float acc = 0.0f;
            #pragma unroll
            for (int t2 = 0; t2 < 16; t2++) {
                int d = (j << 4) + t2;
                float r = S.R[d][m];
                float gg = S.G0[d][m] + S.G1[d][m];
                acc += (r > 0.0f) ? S.Wz[c][d] * gg : 0.0f;
            }
            acc += __shfl_xor_sync(0xffffffffu, acc, 1);
            acc += __shfl_xor_sync(0xffffffffu, acc, 2);
            acc += __shfl_xor_sync(0xffffffffu, acc, 4);
            if (j == 0) {
                // partitionable threefry bits: counter64 = flat idx (hi=0, lo=idx)
                uint2 sk = g_sub[s];
                uint32_t idx = (uint32_t)(2 * (b0 + m) + c);
                uint32_t b1, b2;
                threefry2x32(sk.x, sk.y, 0u, idx, b1, b2);
                float noise = jax_normal_from_bits(b1 ^ b2);
                S.Z[m][c] = S.Z[m][c] - 0.005f * acc + 0.1f * noise;
            }
        }
        __syncthreads();
    }

    if (tid < MT) out[b0 + tid] = S.Z[tid][1];
}

// ---------------------------------------------------------------------------
extern "C" void kernel_launch(void* const* d_in, const int* in_sizes, int n_in,
                              void* d_out, int out_size) {
    (void)in_sizes; (void)n_in; (void)out_size;
    const float* x    = (const float*)d_in[0];
    const float* tv   = (const float*)d_in[1];
    const float* B    = (const float*)d_in[2];
    const float* Win  = (const float*)d_in[3];
    const float* bin  = (const float*)d_in[4];
    const float* WT1  = (const float*)d_in[5];
    const float* bT1  = (const float*)d_in[6];
    const float* WT2  = (const float*)d_in[7];
    const float* WY1  = (const float*)d_in[9];
    const float* bY1  = (const float*)d_in[10];
    const float* WY2  = (const float*)d_in[11];
    float* out = (float*)d_out;

    cudaFuncSetAttribute(main_kernel, cudaFuncAttributeMaxDynamicSharedMemorySize,
                         (int)sizeof(Smem));
    prep_kernel<<<1, 128>>>(B);
    main_kernel<<<NBLOCKS, NTHREADS, sizeof(Smem)>>>(x, tv, Win, bin, WT1, bT1, WT2,
                                                     WY1, bY1, WY2, out);
}

// round 5
// speedup vs baseline: 1.0715x; 1.0715x over previous
#include <cuda_runtime.h>
#include <cuda_bf16.h>
#include <cstdint>

// ============================================================================
// GNN_EBM Langevin sampler, collapsed analytic form + packed f32x2 FMA GEMMs.
//
// Identity: with s_i = 1 + rowsum(A)_i/66 > 0, q_i = s_i + (A s)_i/66 > 0:
//   h2[:,i] = q_i * relu(h0),  h0 = x@W_in[:64] + z@W_in[64:66] + b_in
//   E = relu(q64 r@WT1 + bT1)@WT2 + relu(q65 r@WY1 + bY1)@WY2 + const
// grad_z E = Wz^T ( 1[h0>0] .* ( Wfold @ (1[a>0] .* vcat) ) )
//
// RNG: JAX partitionable threefry:
//   split(key,20):  subkey[i] = threefry2x32(k, 0, i)
//   bits32 elem j:  o0^o1 of threefry2x32(subkey, 0, j)
// then uniform [-0.99999994,1) -> sqrt(2)*erfinv (XLA Giles poly).
//
// GEMM phases use fma.rn.f32x2 (FFMA2): pairs along the sample axis come free
// from 16B LDS; weight scalars are dup-packed. 2048 FFMA2/warp/step/phase,
// 2 warps/SMSP -> fma-pipe-bound at 2x scalar rate.
// ============================================================================

#define MT       32
#define NTHREADS 512
#define NSTEPS   20
#define NBLOCKS  (8192 / MT)
#define WSTRIDE  258   // bf16 elements per W row (padded)

__device__ float g_q[2];
__device__ uint2 g_sub[NSTEPS];

// ---------------------------------------------------------------------------
// packed f32x2 helpers
// ---------------------------------------------------------------------------
__device__ __forceinline__ void ffma2(uint64_t& d, uint64_t a, uint64_t b) {
    asm("fma.rn.f32x2 %0, %1, %2, %0;" : "+l"(d) : "l"(a), "l"(b));
}
__device__ __forceinline__ uint64_t pack2(float lo, float hi) {
    uint64_t r;
    asm("mov.b64 %0, {%1, %2};" : "=l"(r) : "f"(lo), "f"(hi));
    return r;
}
__device__ __forceinline__ void unpack2(uint64_t v, float& lo, float& hi) {
    asm("mov.b64 {%0, %1}, %2;" : "=f"(lo), "=f"(hi) : "l"(v));
}
__device__ __forceinline__ float bf16lo(uint32_t w) { return __uint_as_float(w << 16); }
__device__ __forceinline__ float bf16hi(uint32_t w) { return __uint_as_float(w & 0xffff0000u); }
__device__ __forceinline__ uint64_t dup2(float v) { return pack2(v, v); }

// ---------------------------------------------------------------------------
// threefry2x32 — 20 rounds, 5 key injections
// ---------------------------------------------------------------------------
__device__ __forceinline__ uint32_t rotl32(uint32_t v, int r) {
    return (v << r) | (v >> (32 - r));
}

__device__ __forceinline__ void threefry2x32(uint32_t k0, uint32_t k1,
                                             uint32_t x0, uint32_t x1,
                                             uint32_t& o0, uint32_t& o1) {
    uint32_t k2 = k0 ^ k1 ^ 0x1BD11BDAu;
    x0 += k0; x1 += k1;
#define TFR(r) { x0 += x1; x1 = rotl32(x1, (r)); x1 ^= x0; }
    TFR(13) TFR(15) TFR(26) TFR(6)
    x0 += k1; x1 += k2 + 1u;
    TFR(17) TFR(29) TFR(16) TFR(24)
    x0 += k2; x1 += k0 + 2u;
    TFR(13) TFR(15) TFR(26) TFR(6)
    x0 += k0; x1 += k1 + 3u;
    TFR(17) TFR(29) TFR(16) TFR(24)
    x0 += k1; x1 += k2 + 4u;
    TFR(13) TFR(15) TFR(26) TFR(6)
    x0 += k2; x1 += k0 + 5u;
#undef TFR
    o0 = x0; o1 = x1;
}

// XLA f32 ErfInv (Giles polynomial)
__device__ __forceinline__ float jax_erfinv(float x) {
    float w = -log1pf(-x * x);
    float p;
    if (w < 5.0f) {
        w = w - 2.5f;
        p = 2.81022636e-08f;
        p = fmaf(p, w, 3.43273939e-07f);
        p = fmaf(p, w, -3.5233877e-06f);
        p = fmaf(p, w, -4.39150654e-06f);
        p = fmaf(p, w, 0.00021858087f);
        p = fmaf(p, w, -0.00125372503f);
        p = fmaf(p, w, -0.00417768164f);
        p = fmaf(p, w, 0.246640727f);
        p = fmaf(p, w, 1.50140941f);
    } else {
        w = sqrtf(w) - 3.0f;
        p = -0.000200214257f;
        p = fmaf(p, w, 0.000100950558f);
        p = fmaf(p, w, 0.00134934322f);
        p = fmaf(p, w, -0.00367342844f);
        p = fmaf(p, w, 0.00573950773f);
        p = fmaf(p, w, -0.0076224613f);
        p = fmaf(p, w, 0.00943887047f);
        p = fmaf(p, w, 1.00167406f);
        p = fmaf(p, w, 2.83297682f);
    }
    return p * x;
}

__device__ __forceinline__ float jax_normal_from_bits(uint32_t bits) {
    float f = __uint_as_float((bits >> 9) | 0x3f800000u) - 1.0f;
    const float lo = -0.99999994f;
    float u = fmaxf(lo, fmaf(f, 2.0f, lo));
    return 1.41421356237f * jax_erfinv(u);
}

// ---------------------------------------------------------------------------
// prep: q scalars + 20 subkeys
// ---------------------------------------------------------------------------
__device__ __forceinline__ float sigm(float v) { return 1.0f / (1.0f + expf(-v)); }

__global__ void prep_kernel(const float* __restrict__ B) {
    __shared__ float sS[66];
    int t = threadIdx.x;

    if (t < 66) {
        float rs = 0.0f;
        for (int k = 0; k < 66; k++) {
            if (k == t) continue;
            if (t == 65 && k < 64) continue;
            rs += sigm(B[t * 66 + k]);
        }
        sS[t] = 1.0f + rs / 66.0f;
    }
    if (t < 20) {
        uint32_t o0, o1;
        threefry2x32(0u, 42u, 0u, (uint32_t)t, o0, o1);
        g_sub[t] = make_uint2(o0, o1);
    }
    __syncthreads();
    if (t == 0) {
        float acc64 = 0.0f;
        for (int j = 0; j < 66; j++)
            if (j != 64) acc64 += sigm(B[64 * 66 + j]) * sS[j];
        float acc65 = sigm(B[65 * 66 + 64]) * sS[64];
        g_q[0] = sS[64] + acc64 / 66.0f;
        g_q[1] = sS[65] + acc65 / 66.0f;
    }
}

// ---------------------------------------------------------------------------
// main persistent kernel
// ---------------------------------------------------------------------------
struct Smem {
    __nv_bfloat16 W[128][WSTRIDE]; // k<128 -> q0*WT1 ; k>=128 -> q1*WY1
    float C[128][36];              // x-part of h0 (+b_in), [d][m]
    float R[128][36];              // relu(h0), [d][m]
    float M[256][36];              // 1[a>0]*vcat, [k][m]  (also prologue scratch)
    float G0[128][36];             // backward partials (k-half 0)
    float G1[128][36];             // backward partials (k-half 1)
    float Wz[2][128];
    float bcat[256];
    float vcat[256];
    float Z[MT][2];
    float Xs[MT][65];
};

__global__ void __launch_bounds__(NTHREADS, 1)
main_kernel(const float* __restrict__ x, const float* __restrict__ tvec,
            const float* __restrict__ Win, const float* __restrict__ bin,
            const float* __restrict__ WT1, const float* __restrict__ bT1,
            const float* __restrict__ WT2,
            const float* __restrict__ WY1, const float* __restrict__ bY1,
            const float* __restrict__ WY2,
            float* __restrict__ out) {
    extern __shared__ unsigned char sraw[];
    Smem& S = *reinterpret_cast<Smem*>(sraw);
    const int tid = threadIdx.x;
    const int b0 = blockIdx.x * MT;
    const float q0 = g_q[0];
    const float q1 = g_q[1];

    // ---- prologue: stage weights ----
    for (int i = tid; i < 128 * 128; i += NTHREADS) {
        int d = i >> 7, k = i & 127;
        S.W[d][k]       = __float2bfloat16(q0 * WT1[i]);
        S.W[d][k + 128] = __float2bfloat16(q1 * WY1[i]);
    }
    float* WinS = &S.M[0][0];                   // scratch: 64x128 f32 = 32KB
    for (int i = tid; i < 64 * 128; i += NTHREADS) WinS[i] = Win[i];
    for (int i = tid; i < MT * 64; i += NTHREADS) {
        int m = i >> 6, e = i & 63;
        S.Xs[m][e] = x[(size_t)(b0 + m) * 64 + e];
    }
    if (tid < 256) {
        S.bcat[tid] = (tid < 128) ? bT1[tid] : bY1[tid - 128];
        S.vcat[tid] = (tid < 128) ? WT2[tid] : WY2[tid - 128];
    }
    if (tid < 128) {
        S.Wz[0][tid] = Win[64 * 128 + tid];
        S.Wz[1][tid] = Win[65 * 128 + tid];
    }
    if (tid < MT) {
        S.Z[tid][0] = tvec[b0 + tid];
        S.Z[tid][1] = 0.0f;
    }
    __syncthreads();

    // ---- C[d][m] = b_in[d] + sum_e Xs[m][e] * Win[e][d] ----
    {
        int d = tid & 127, m0 = (tid >> 7) << 3;
        float acc[8];
        float bv = bin[d];
        #pragma unroll
        for (int i = 0; i < 8; i++) acc[i] = bv;
        for (int e = 0; e < 64; e++) {
            float w = WinS[(e << 7) + d];
            #pragma unroll
            for (int i = 0; i < 8; i++) acc[i] = fmaf(S.Xs[m0 + i][e], w, acc[i]);
        }
        #pragma unroll
        for (int i = 0; i < 8; i++) S.C[d][m0 + i] = acc[i];
    }
    __syncthreads();

    // ---- Langevin steps ----
    for (int s = 0; s < NSTEPS; s++) {
        // Phase A: R = relu(C + z0*Wz0 + z1*Wz1)
        {
            int d = tid >> 2, m0 = (tid & 3) << 3;
            float wz0 = S.Wz[0][d], wz1 = S.Wz[1][d];
            #pragma unroll
            for (int i = 0; i < 8; i++) {
                int m = m0 + i;
                float h = fmaf(S.Z[m][1], wz1, fmaf(S.Z[m][0], wz0, S.C[d][m]));
                S.R[d][m] = fmaxf(h, 0.0f);
            }
        }
        __syncthreads();

        // Phase B (256 thr): a[m][k] = bcat[k] + sum_d R[d][m]*W[d][k]
        //                    M[k][m] = 1[a>0]*vcat[k]     (FFMA2, m-paired)
        if (tid < 256) {
            int kg = tid & 63, mg = tid >> 6;
            int k0 = kg << 2, m0 = mg << 3;
            uint64_t acc[4][4];                 // [kj][mpair]
            #pragma unroll
            for (int j = 0; j < 4; j++) {
                uint64_t bv = dup2(S.bcat[k0 + j]);
                #pragma unroll
                for (int p = 0; p < 4; p++) acc[j][p] = bv;
            }
            #pragma unroll 4
            for (int d = 0; d < 128; d++) {
                ulonglong2 ra = *reinterpret_cast<const ulonglong2*>(&S.R[d][m0]);
                ulonglong2 rb = *reinterpret_cast<const ulonglong2*>(&S.R[d][m0 + 4]);
                uint32_t w01 = *reinterpret_cast<const uint32_t*>(&S.W[d][k0]);
                uint32_t w23 = *reinterpret_cast<const uint32_t*>(&S.W[d][k0 + 2]);
                uint64_t w0 = dup2(bf16lo(w01));
                uint64_t w1 = dup2(bf16hi(w01));
                uint64_t w2 = dup2(bf16lo(w23));
                uint64_t w3 = dup2(bf16hi(w23));
                ffma2(acc[0][0], ra.x, w0); ffma2(acc[0][1], ra.y, w0);
                ffma2(acc[0][2], rb.x, w0); ffma2(acc[0][3], rb.y, w0);
                ffma2(acc[1][0], ra.x, w1); ffma2(acc[1][1], ra.y, w1);
                ffma2(acc[1][2], rb.x, w1); ffma2(acc[1][3], rb.y, w1);
                ffma2(acc[2][0], ra.x, w2); ffma2(acc[2][1], ra.y, w2);
                ffma2(acc[2][2], rb.x, w2); ffma2(acc[2][3], rb.y, w2);
                ffma2(acc[3][0], ra.x, w3); ffma2(acc[3][1], ra.y, w3);
                ffma2(acc[3][2], rb.x, w3); ffma2(acc[3][3], rb.y, w3);
            }
            #pragma unroll
            for (int j = 0; j < 4; j++) {
                float v = S.vcat[k0 + j];
                #pragma unroll
                for (int p = 0; p < 4; p++) {
                    float lo, hi;
                    unpack2(acc[j][p], lo, hi);
                    float slo = lo > 0.0f ? v : 0.0f;
                    float shi = hi > 0.0f ? v : 0.0f;
                    *reinterpret_cast<uint64_t*>(&S.M[k0 + j][m0 + 2 * p]) = pack2(slo, shi);
                }
            }
        }
        __syncthreads();

        // Phase C (256 thr): G_h[d][m] = sum_{k in half h} W[d][k]*M[k][m]
        if (tid < 256) {
            int half = tid >> 7;
            int idx = tid & 127;
            int d0 = (idx >> 2) << 2, m0 = (idx & 3) << 3;
            int kb = half << 7;
            uint64_t acc[4][4];                 // [di][mpair]
            #pragma unroll
            for (int i = 0; i < 4; i++)
                #pragma unroll
                for (int p = 0; p < 4; p++) acc[i][p] = 0ull;
            #pragma unroll 2
            for (int kk = 0; kk < 128; kk += 2) {
                int k = kb + kk;
                ulonglong2 ma  = *reinterpret_cast<const ulonglong2*>(&S.M[k][m0]);
                ulonglong2 ma2 = *reinterpret_cast<const ulonglong2*>(&S.M[k][m0 + 4]);
                ulonglong2 mb  = *reinterpret_cast<const ulonglong2*>(&S.M[k + 1][m0]);
                ulonglong2 mb2 = *reinterpret_cast<const ulonglong2*>(&S.M[k + 1][m0 + 4]);
                #pragma unroll
                for (int di = 0; di < 4; di++) {
                    uint32_t w = *reinterpret_cast<const uint32_t*>(&S.W[d0 + di][k]);
                    uint64_t wl = dup2(bf16lo(w));
                    uint64_t wh = dup2(bf16hi(w));
                    ffma2(acc[di][0], ma.x,  wl); ffma2(acc[di][0], mb.x,  wh);
                    ffma2(acc[di][1], ma.y,  wl); ffma2(acc[di][1], mb.y,  wh);
                    ffma2(acc[di][2], ma2.x, wl); ffma2(acc[di][2], mb2.x, wh);
                    ffma2(acc[di][3], ma2.y, wl); ffma2(acc[di][3], mb2.y, wh);
                }
            }
            float (*G)[36] = half ? S.G1 : S.G0;
            #pragma unroll
            for (int di = 0; di < 4; di++)
                #pragma unroll
                for (int p = 0; p < 4; p++)
                    *reinterpret_cast<uint64_t*>(&G[d0 + di][m0 + 2 * p]) = acc[di][p];
        }
        __syncthreads();

        // Phase D: gz[m][c] = sum_d Wz[c][d]*1[R>0]*(G0+G1); z update + noise
        {
            int g = tid >> 3, j = tid & 7;
            int m = g >> 1, c = g & 1;
            float acc = 0.0f;
            #pragma unroll
            for (int t2 = 0; t2 < 16; t2++) {
                int d = (j << 4) + t2;
                float r = S.R[d][m];
                float gg = S.G0[d][m] + S.G1[d][m];
                acc += (r > 0.0f) ? S.Wz[c][d] * gg : 0.0f;
            }
            acc += __shfl_xor_sync(0xffffffffu, acc, 1);
            acc += __shfl_xor_sync(0xffffffffu, acc, 2);
            acc += __shfl_xor_sync(0xffffffffu, acc, 4);
            if (j == 0) {
                uint2 sk = g_sub[s];
                uint32_t idx = (uint32_t)(2 * (b0 + m) + c);
                uint32_t b1, b2;
                threefry2x32(sk.x, sk.y, 0u, idx, b1, b2);
                float noise = jax_normal_from_bits(b1 ^ b2);
                S.Z[m][c] = S.Z[m][c] - 0.005f * acc + 0.1f * noise;
            }
        }
        __syncthreads();
    }

    if (tid < MT) out[b0 + tid] = S.Z[tid][1];
}

// ---------------------------------------------------------------------------
extern "C" void kernel_launch(void* const* d_in, const int* in_sizes, int n_in,
                              void* d_out, int out_size) {
    (void)in_sizes; (void)n_in; (void)out_size;
    const float* x    = (const float*)d_in[0];
    const float* tv   = (const float*)d_in[1];
    const float* B    = (const float*)d_in[2];
    const float* Win  = (const float*)d_in[3];
    const float* bin  = (const float*)d_in[4];
    const float* WT1  = (const float*)d_in[5];
    const float* bT1  = (const float*)d_in[6];
    const float* WT2  = (const float*)d_in[7];
    const float* WY1  = (const float*)d_in[9];
    const float* bY1  = (const float*)d_in[10];
    const float* WY2  = (const float*)d_in[11];
    float* out = (float*)d_out;

    cudaFuncSetAttribute(main_kernel, cudaFuncAttributeMaxDynamicSharedMemorySize,
                         (int)sizeof(Smem));
    prep_kernel<<<1, 128>>>(B);
    main_kernel<<<NBLOCKS, NTHREADS, sizeof(Smem)>>>(x, tv, Win, bin, WT1, bT1, WT2,
                                                     WY1, bY1, WY2, out);
}